// round 8
// baseline (speedup 1.0000x reference)
#include <cuda_runtime.h>

#define NUM_SKILLS 300
#define EMB 256
#define CD 64
#define BB 512
#define SS 200
#define RPB_OUT 16                 // rows per block in store kernel

// Scratch (no allocations allowed).
__device__ float4 g_scal[BB * SS];         // {qf, att, mast, valid}
__device__ float  g_A[EMB], g_B[EMB], g_C[EMB], g_D[EMB];

// ---------------------------------------------------------------------------
// K1, grid 544: blocks 0..511 = per-row counts (ONE block per batch row, done
// once, warp-parallel ballot/popc: warp w owns rows w+8*rr, rr<25).
// Blocks 512..543 = coefficient blocks, one warp per e (proven ~1us scheme):
//   out[b,s,e] = qf*A[e] + att*B[e] + mast*C[e] + D[e]
// ---------------------------------------------------------------------------
__global__ void __launch_bounds__(256) prep_kernel(
    const int* __restrict__ q, const int* __restrict__ r,
    const float* __restrict__ skill_w, const float* __restrict__ skill_b,
    const float* __restrict__ att_w,   const float* __restrict__ att_b,
    const float* __restrict__ mast_w,  const float* __restrict__ mast_b,
    const float* __restrict__ proj_w,  const float* __restrict__ proj_b)
{
    const int blk  = blockIdx.x;
    const int t    = threadIdx.x;
    const int w    = t >> 5;
    const int lane = t & 31;

    if (blk < BB) {
        // ---- counts for batch row `blk` ----
        __shared__ int pack[SS];   // qc | valid<<9 | r<<10
        if (t < SS) {
            const int qraw = q[blk * SS + t];
            const int v  = (qraw >= 0) & (qraw < NUM_SKILLS);
            int qc = qraw < 0 ? 0 : (qraw > NUM_SKILLS - 1 ? NUM_SKILLS - 1 : qraw);
            pack[t] = qc | (v << 9) | ((r[blk * SS + t] & 1) << 10);
        }
        __syncthreads();

        #pragma unroll
        for (int rr = 0; rr < SS / 8; ++rr) {      // 25 rows per warp
            const int s   = w + rr * 8;            // interleaved -> balanced
            const int w0  = pack[s];               // broadcast
            const int myq = w0 & 0x1FF;
            int att = 0, cor = 0;
            const int nchunk = (s + 32) >> 5;      // ceil((s+1)/32)
            for (int k = 0; k < nchunk; ++k) {
                const int tp  = (k << 5) + lane;
                const int idx = tp <= s ? tp : s;
                const int pw  = pack[idx];
                const bool in = tp <= s;
                const bool m  = in && (((pw & 0x1FF) == myq) & ((pw >> 9) & 1));
                att += __popc(__ballot_sync(0xFFFFFFFF, m));
                cor += __popc(__ballot_sync(0xFFFFFFFF, m && ((pw >> 10) & 1)));
            }
            if (lane == 0) {
                const float attf = (float)att;
                const float mast = (float)cor / fmaxf(attf, 1.0f);
                const float vf   = ((w0 >> 9) & 1) ? 1.0f : 0.0f;
                g_scal[blk * SS + s] = make_float4((float)myq, attf, mast, vf);
            }
        }
    } else {
        // ---- coefficients: e = (blk-512)*8 + warp ----
        const int e   = (blk - BB) * 8 + w;        // 0..255
        const int chi = lane + 32;

        const float wlo = (lane < 21) ? skill_w[lane] : att_w[lane - 21];
        const float blo = (lane < 21) ? skill_b[lane] : att_b[lane - 21];
        const float whi = (chi  < 42) ? att_w[chi - 21] : mast_w[chi - 42];
        const float bhi = (chi  < 42) ? att_b[chi - 21] : mast_b[chi - 42];

        const float p0 = proj_w[e * CD + lane];
        const float p1 = proj_w[e * CD + chi];

        const bool loA = lane < 21;
        const bool hiB = chi  < 42;

        float av = loA ? p0 * wlo : 0.0f;
        float bv = (loA ? 0.0f : p0 * wlo) + (hiB ? p1 * whi : 0.0f);
        float cv = hiB ? 0.0f : p1 * whi;
        float dv = fmaf(p0, blo, p1 * bhi);

        #pragma unroll
        for (int off = 16; off > 0; off >>= 1) {
            av += __shfl_xor_sync(0xFFFFFFFF, av, off);
            bv += __shfl_xor_sync(0xFFFFFFFF, bv, off);
            cv += __shfl_xor_sync(0xFFFFFFFF, cv, off);
            dv += __shfl_xor_sync(0xFFFFFFFF, dv, off);
        }
        if (lane == 0) {
            g_A[e] = av; g_B[e] = bv; g_C[e] = cv;
            g_D[e] = dv + proj_b[e];
        }
    }
}

// ---------------------------------------------------------------------------
// K2: pure store kernel. 6400 blocks x 256 threads, 16 rows per block,
// 4 rows per thread. Thread owns e4 = t&63 with coefficients in registers;
// scalar loads are warp-uniform broadcasts; stores 512B/warp coalesced,
// streaming (.cs). Low register count -> high occupancy for write MLP.
// ---------------------------------------------------------------------------
__global__ void __launch_bounds__(256) out_kernel(float* __restrict__ out)
{
    const int e4  = threadIdx.x & 63;
    const int l4  = threadIdx.x >> 6;              // 0..3
    const int bs0 = blockIdx.x * RPB_OUT;

    const float4 a  = __ldg(&reinterpret_cast<const float4*>(g_A)[e4]);
    const float4 bc = __ldg(&reinterpret_cast<const float4*>(g_B)[e4]);
    const float4 cc = __ldg(&reinterpret_cast<const float4*>(g_C)[e4]);
    const float4 dc = __ldg(&reinterpret_cast<const float4*>(g_D)[e4]);

    float4 s[4];
    #pragma unroll
    for (int i = 0; i < 4; ++i)
        s[i] = __ldg(&g_scal[bs0 + l4 + i * 4]);   // warp-uniform broadcast

    float4* __restrict__ out4 = reinterpret_cast<float4*>(out);
    const int base = bs0 * (EMB / 4) + e4;

    #pragma unroll
    for (int i = 0; i < 4; ++i) {
        const int row = l4 + i * 4;                // 0..15
        float4 o;
        if (s[i].w != 0.0f) {
            o.x = fmaf(s[i].x, a.x, fmaf(s[i].y, bc.x, fmaf(s[i].z, cc.x, dc.x)));
            o.y = fmaf(s[i].x, a.y, fmaf(s[i].y, bc.y, fmaf(s[i].z, cc.y, dc.y)));
            o.z = fmaf(s[i].x, a.z, fmaf(s[i].y, bc.z, fmaf(s[i].z, cc.z, dc.z)));
            o.w = fmaf(s[i].x, a.w, fmaf(s[i].y, bc.w, fmaf(s[i].z, cc.w, dc.w)));
        } else {
            o = make_float4(0.f, 0.f, 0.f, 0.f);
        }
        __stcs(&out4[base + row * (EMB / 4)], o);
    }
}

// Input order (metadata): 0=q 1=r 2=qry(unused) 3=skill_w 4=skill_b
// 5=att_w 6=att_b 7=mast_w 8=mast_b 9=proj_w 10=proj_b
extern "C" void kernel_launch(void* const* d_in, const int* in_sizes, int n_in,
                              void* d_out, int out_size)
{
    const int*   q       = (const int*)d_in[0];
    const int*   r       = (const int*)d_in[1];
    const float* skill_w = (const float*)d_in[3];
    const float* skill_b = (const float*)d_in[4];
    const float* att_w   = (const float*)d_in[5];
    const float* att_b   = (const float*)d_in[6];
    const float* mast_w  = (const float*)d_in[7];
    const float* mast_b  = (const float*)d_in[8];
    const float* proj_w  = (const float*)d_in[9];
    const float* proj_b  = (const float*)d_in[10];
    float* out = (float*)d_out;

    prep_kernel<<<BB + EMB / 8, 256>>>(q, r, skill_w, skill_b, att_w, att_b,
                                       mast_w, mast_b, proj_w, proj_b);

    out_kernel<<<(BB * SS) / RPB_OUT, 256>>>(out);   // 6400 blocks
}

// round 9
// speedup vs baseline: 1.3913x; 1.3913x over previous
#include <cuda_runtime.h>

#define NUM_SKILLS 300
#define EMB 256
#define CD 64
#define BB 512
#define SS 200
#define SEGLEN 25                 // histogram segment length (8 segs * 25 = 200)
#define RPB_OUT 32                // rows per block in store kernel

// Scratch (no allocations allowed).
__device__ float4 g_scal[BB * SS];         // {qf, att, mast, valid}
__device__ float  g_A[EMB], g_B[EMB], g_C[EMB], g_D[EMB];

// ---------------------------------------------------------------------------
// K1, grid 544.
// Blocks 0..511: per-row counts via SEGMENT HISTOGRAMS (one block per batch
//   row). Phase A: warp w histograms its 25 elements into hist[w][key]
//   (att | cor<<16 packed, shared atomics). Phase B: thread t resolves row t:
//   base = sum of hist[g'][key_t] for segments g' before its own, plus a
//   <=25-step within-segment scan. ~250 instr/warp total.
// Blocks 512..543: einsum-collapse coefficients, one warp per e:
//   out[b,s,e] = qf*A[e] + att*B[e] + mast*C[e] + valid*D[e]
// ---------------------------------------------------------------------------
__global__ void __launch_bounds__(256) prep_kernel(
    const int* __restrict__ q, const int* __restrict__ r,
    const float* __restrict__ skill_w, const float* __restrict__ skill_b,
    const float* __restrict__ att_w,   const float* __restrict__ att_b,
    const float* __restrict__ mast_w,  const float* __restrict__ mast_b,
    const float* __restrict__ proj_w,  const float* __restrict__ proj_b)
{
    const int blk  = blockIdx.x;
    const int t    = threadIdx.x;
    const int w    = t >> 5;
    const int lane = t & 31;

    if (blk < BB) {
        __shared__ int           key[SS];        // 0..299 valid, 300 invalid
        __shared__ unsigned char rbit[SS];
        __shared__ unsigned      hist[8][NUM_SKILLS + 4];  // att | cor<<16

        // zero histograms (8*304 = 2432 words)
        unsigned* hz = &hist[0][0];
        for (int i = t; i < 8 * (NUM_SKILLS + 4); i += 256) hz[i] = 0;

        if (t < SS) {
            const int qraw = q[blk * SS + t];
            const int v = (qraw >= 0) & (qraw < NUM_SKILLS);
            int qc = qraw < 0 ? 0 : (qraw > NUM_SKILLS - 1 ? NUM_SKILLS - 1 : qraw);
            key[t]  = v ? qc : NUM_SKILLS;       // sentinel never matches valid
            rbit[t] = (unsigned char)(r[blk * SS + t] & 1);
        }
        __syncthreads();

        // Phase A: segment histograms. Warp w owns elements [25w, 25w+25).
        if (lane < SEGLEN) {
            const int e = w * SEGLEN + lane;
            atomicAdd(&hist[w][key[e]], 1u + ((unsigned)rbit[e] << 16));
        }
        __syncthreads();

        // Phase B: resolve each row.
        if (t < SS) {
            const int g   = t / SEGLEN;
            const int myk = key[t];
            unsigned acc = 0;
            for (int gp = 0; gp < g; ++gp) acc += hist[gp][myk];
            int att = (int)(acc & 0xFFFFu);
            int cor = (int)(acc >> 16);
            for (int e = g * SEGLEN; e <= t; ++e) {
                const int m = (key[e] == myk);
                att += m;
                cor += m & (int)rbit[e];
            }
            const float attf = (float)att;
            const float mast = (float)cor / fmaxf(attf, 1.0f);
            g_scal[blk * SS + t] = (myk < NUM_SKILLS)
                ? make_float4((float)myk, attf, mast, 1.0f)
                : make_float4(0.f, 0.f, 0.f, 0.f);
        }
    } else {
        // ---- coefficients: e = (blk-512)*8 + warp ----
        const int e   = (blk - BB) * 8 + w;      // 0..255
        const int chi = lane + 32;

        const float wlo = (lane < 21) ? skill_w[lane] : att_w[lane - 21];
        const float blo = (lane < 21) ? skill_b[lane] : att_b[lane - 21];
        const float whi = (chi  < 42) ? att_w[chi - 21] : mast_w[chi - 42];
        const float bhi = (chi  < 42) ? att_b[chi - 21] : mast_b[chi - 42];

        const float p0 = proj_w[e * CD + lane];
        const float p1 = proj_w[e * CD + chi];

        const bool loA = lane < 21;
        const bool hiB = chi  < 42;

        float av = loA ? p0 * wlo : 0.0f;
        float bv = (loA ? 0.0f : p0 * wlo) + (hiB ? p1 * whi : 0.0f);
        float cv = hiB ? 0.0f : p1 * whi;
        float dv = fmaf(p0, blo, p1 * bhi);

        #pragma unroll
        for (int off = 16; off > 0; off >>= 1) {
            av += __shfl_xor_sync(0xFFFFFFFF, av, off);
            bv += __shfl_xor_sync(0xFFFFFFFF, bv, off);
            cv += __shfl_xor_sync(0xFFFFFFFF, cv, off);
            dv += __shfl_xor_sync(0xFFFFFFFF, dv, off);
        }
        if (lane == 0) {
            g_A[e] = av; g_B[e] = bv; g_C[e] = cv;
            g_D[e] = dv + proj_b[e];
        }
    }
}

// ---------------------------------------------------------------------------
// K2: pure store kernel. 3200 blocks x 256 threads, 32 rows/block,
// 8 rows/thread (R4's best-measured shape). Row scalars staged in SHARED
// (saves 32 regs vs per-thread prefetch -> occupancy cap 64 warps/SM).
// Thread owns e4 = t&63 with its 4 coefficient float4s in registers.
// Branchless: valid flag (s.w) multiplies the D term.
// ---------------------------------------------------------------------------
__global__ void __launch_bounds__(256) out_kernel(float* __restrict__ out)
{
    __shared__ float4 sscal[RPB_OUT];

    const int t   = threadIdx.x;
    const int e4  = t & 63;
    const int l4  = t >> 6;                      // 0..3
    const int bs0 = blockIdx.x * RPB_OUT;

    // coefficient fetch (L1/L2-hot after first wave)
    const float4 a  = __ldg(&reinterpret_cast<const float4*>(g_A)[e4]);
    const float4 bc = __ldg(&reinterpret_cast<const float4*>(g_B)[e4]);
    const float4 cc = __ldg(&reinterpret_cast<const float4*>(g_C)[e4]);
    const float4 dc = __ldg(&reinterpret_cast<const float4*>(g_D)[e4]);

    if (t < RPB_OUT) sscal[t] = g_scal[bs0 + t];
    __syncthreads();

    float4* __restrict__ out4 = reinterpret_cast<float4*>(out);
    const int base = bs0 * (EMB / 4) + e4;

    #pragma unroll
    for (int i = 0; i < RPB_OUT / 4; ++i) {
        const int row = l4 + i * 4;              // 0..31, uniform per warp
        const float4 s = sscal[row];             // LDS broadcast
        float4 o;
        o.x = fmaf(s.x, a.x, fmaf(s.y, bc.x, fmaf(s.z, cc.x, s.w * dc.x)));
        o.y = fmaf(s.x, a.y, fmaf(s.y, bc.y, fmaf(s.z, cc.y, s.w * dc.y)));
        o.z = fmaf(s.x, a.z, fmaf(s.y, bc.z, fmaf(s.z, cc.z, s.w * dc.z)));
        o.w = fmaf(s.x, a.w, fmaf(s.y, bc.w, fmaf(s.z, cc.w, s.w * dc.w)));
        out4[base + row * (EMB / 4)] = o;
    }
}

// Input order (metadata): 0=q 1=r 2=qry(unused) 3=skill_w 4=skill_b
// 5=att_w 6=att_b 7=mast_w 8=mast_b 9=proj_w 10=proj_b
extern "C" void kernel_launch(void* const* d_in, const int* in_sizes, int n_in,
                              void* d_out, int out_size)
{
    const int*   q       = (const int*)d_in[0];
    const int*   r       = (const int*)d_in[1];
    const float* skill_w = (const float*)d_in[3];
    const float* skill_b = (const float*)d_in[4];
    const float* att_w   = (const float*)d_in[5];
    const float* att_b   = (const float*)d_in[6];
    const float* mast_w  = (const float*)d_in[7];
    const float* mast_b  = (const float*)d_in[8];
    const float* proj_w  = (const float*)d_in[9];
    const float* proj_b  = (const float*)d_in[10];
    float* out = (float*)d_out;

    prep_kernel<<<BB + EMB / 8, 256>>>(q, r, skill_w, skill_b, att_w, att_b,
                                       mast_w, mast_b, proj_w, proj_b);

    out_kernel<<<(BB * SS) / RPB_OUT, 256>>>(out);   // 3200 blocks
}

// round 10
// speedup vs baseline: 1.4167x; 1.0182x over previous
#include <cuda_runtime.h>

#define NUM_SKILLS 300
#define EMB 256
#define CD 64
#define BB 512
#define SS 200
#define RPB_OUT 64                 // rows per block in store kernel (flat rows)
#define NSEG 7                     // 7 segments of 32 cover 224 >= 200

// Scratch (no allocations allowed).
__device__ float4 g_scal[BB * SS];         // {qf, att, mast, valid}
__device__ float  g_A[EMB], g_B[EMB], g_C[EMB], g_D[EMB];

// ---------------------------------------------------------------------------
// K1, grid 544.
// Blocks 0..511: counts for one batch row, warp-segment formulation.
//   Element e = threadIdx.x (segment w = t>>5, warps 0..6 hold rows 0..223).
//   Within-segment running counts: __match_any_sync + popc(lanemask_le).
//   Cross-segment: per-warp histogram (att | cor<<16) published via shared
//   atomics; row in segment w gathers hist[0..w-1][key]. ~30 instr/warp.
// Blocks 512..543: einsum-collapse coefficients, one warp per e:
//   out[b,s,e] = qf*A[e] + att*B[e] + mast*C[e] + valid*D[e]
// ---------------------------------------------------------------------------
__global__ void __launch_bounds__(256) prep_kernel(
    const int* __restrict__ q, const int* __restrict__ r,
    const float* __restrict__ skill_w, const float* __restrict__ skill_b,
    const float* __restrict__ att_w,   const float* __restrict__ att_b,
    const float* __restrict__ mast_w,  const float* __restrict__ mast_b,
    const float* __restrict__ proj_w,  const float* __restrict__ proj_b)
{
    const int blk  = blockIdx.x;
    const int t    = threadIdx.x;
    const int w    = t >> 5;
    const int lane = t & 31;

    if (blk < BB) {
        __shared__ unsigned hist[NSEG][NUM_SKILLS + 4];   // att | cor<<16

        // zero histograms (7*304 = 2128 words)
        unsigned* hz = &hist[0][0];
        for (int i = t; i < NSEG * (NUM_SKILLS + 4); i += 256) hz[i] = 0;

        // element e == t; load inputs (coalesced)
        int valid = 0, key = 0x8000 | t, rb = 0;
        if (t < SS) {
            const int qraw = q[blk * SS + t];
            valid = (qraw >= 0) & (qraw < NUM_SKILLS);
            if (valid) {
                key = qraw;
                rb  = r[blk * SS + t] & 1;
            }
        }
        __syncthreads();   // histograms zeroed

        // within-segment running counts (self included)
        const unsigned mask  = __match_any_sync(0xFFFFFFFFu, key);
        const unsigned rball = __ballot_sync(0xFFFFFFFFu, rb);
        const unsigned le    = (lane == 31) ? 0xFFFFFFFFu : ((2u << lane) - 1u);
        int att = __popc(mask & le);
        int cor = __popc(mask & le & rball);

        // publish this segment's histogram
        if (valid) atomicAdd(&hist[w][key], 1u | ((unsigned)rb << 16));
        __syncthreads();

        // gather prior segments
        if (t < SS && valid) {
            unsigned acc = 0;
            for (int gp = 0; gp < w; ++gp) acc += hist[gp][key];
            att += (int)(acc & 0xFFFFu);
            cor += (int)(acc >> 16);
            const float attf = (float)att;
            g_scal[blk * SS + t] =
                make_float4((float)key, attf, (float)cor / fmaxf(attf, 1.0f), 1.0f);
        } else if (t < SS) {
            g_scal[blk * SS + t] = make_float4(0.f, 0.f, 0.f, 0.f);
        }
    } else {
        // ---- coefficients: e = (blk-512)*8 + warp ----
        const int e   = (blk - BB) * 8 + w;      // 0..255
        const int chi = lane + 32;

        const float wlo = (lane < 21) ? skill_w[lane] : att_w[lane - 21];
        const float blo = (lane < 21) ? skill_b[lane] : att_b[lane - 21];
        const float whi = (chi  < 42) ? att_w[chi - 21] : mast_w[chi - 42];
        const float bhi = (chi  < 42) ? att_b[chi - 21] : mast_b[chi - 42];

        const float p0 = proj_w[e * CD + lane];
        const float p1 = proj_w[e * CD + chi];

        const bool loA = lane < 21;
        const bool hiB = chi  < 42;

        float av = loA ? p0 * wlo : 0.0f;
        float bv = (loA ? 0.0f : p0 * wlo) + (hiB ? p1 * whi : 0.0f);
        float cv = hiB ? 0.0f : p1 * whi;
        float dv = fmaf(p0, blo, p1 * bhi);

        #pragma unroll
        for (int off = 16; off > 0; off >>= 1) {
            av += __shfl_xor_sync(0xFFFFFFFF, av, off);
            bv += __shfl_xor_sync(0xFFFFFFFF, bv, off);
            cv += __shfl_xor_sync(0xFFFFFFFF, cv, off);
            dv += __shfl_xor_sync(0xFFFFFFFF, dv, off);
        }
        if (lane == 0) {
            g_A[e] = av; g_B[e] = bv; g_C[e] = cv;
            g_D[e] = dv + proj_b[e];
        }
    }
}

// ---------------------------------------------------------------------------
// K2: pure store kernel. 1600 blocks x 256 threads, 64 flat rows per block
// (rows need not align to batch boundaries). Row scalars staged in shared;
// thread owns e4 = t&63 with coefficients in registers; 16 iterations of
// (1 broadcast LDS + 12 FMA + 1 STG.128). Coefficient-load L1 wavefronts
// amortized over 2x more stored bytes than R9.
// ---------------------------------------------------------------------------
__global__ void __launch_bounds__(256) out_kernel(float* __restrict__ out)
{
    __shared__ float4 sscal[RPB_OUT];

    const int t   = threadIdx.x;
    const int e4  = t & 63;
    const int l4  = t >> 6;                      // 0..3
    const int bs0 = blockIdx.x * RPB_OUT;        // flat row base

    const float4 a  = __ldg(&reinterpret_cast<const float4*>(g_A)[e4]);
    const float4 bc = __ldg(&reinterpret_cast<const float4*>(g_B)[e4]);
    const float4 cc = __ldg(&reinterpret_cast<const float4*>(g_C)[e4]);
    const float4 dc = __ldg(&reinterpret_cast<const float4*>(g_D)[e4]);

    if (t < RPB_OUT) sscal[t] = g_scal[bs0 + t];
    __syncthreads();

    float4* __restrict__ out4 = reinterpret_cast<float4*>(out);
    const int base = bs0 * (EMB / 4) + e4;

    #pragma unroll
    for (int i = 0; i < RPB_OUT / 4; ++i) {
        const int row = l4 + i * 4;              // 0..63, uniform per warp
        const float4 s = sscal[row];             // LDS broadcast
        float4 o;
        o.x = fmaf(s.x, a.x, fmaf(s.y, bc.x, fmaf(s.z, cc.x, s.w * dc.x)));
        o.y = fmaf(s.x, a.y, fmaf(s.y, bc.y, fmaf(s.z, cc.y, s.w * dc.y)));
        o.z = fmaf(s.x, a.z, fmaf(s.y, bc.z, fmaf(s.z, cc.z, s.w * dc.z)));
        o.w = fmaf(s.x, a.w, fmaf(s.y, bc.w, fmaf(s.z, cc.w, s.w * dc.w)));
        out4[base + row * (EMB / 4)] = o;
    }
}

// Input order (metadata): 0=q 1=r 2=qry(unused) 3=skill_w 4=skill_b
// 5=att_w 6=att_b 7=mast_w 8=mast_b 9=proj_w 10=proj_b
extern "C" void kernel_launch(void* const* d_in, const int* in_sizes, int n_in,
                              void* d_out, int out_size)
{
    const int*   q       = (const int*)d_in[0];
    const int*   r       = (const int*)d_in[1];
    const float* skill_w = (const float*)d_in[3];
    const float* skill_b = (const float*)d_in[4];
    const float* att_w   = (const float*)d_in[5];
    const float* att_b   = (const float*)d_in[6];
    const float* mast_w  = (const float*)d_in[7];
    const float* mast_b  = (const float*)d_in[8];
    const float* proj_w  = (const float*)d_in[9];
    const float* proj_b  = (const float*)d_in[10];
    float* out = (float*)d_out;

    prep_kernel<<<BB + EMB / 8, 256>>>(q, r, skill_w, skill_b, att_w, att_b,
                                       mast_w, mast_b, proj_w, proj_b);

    out_kernel<<<(BB * SS) / RPB_OUT, 256>>>(out);   // 1600 blocks
}